// round 3
// baseline (speedup 1.0000x reference)
#include <cuda_runtime.h>
#include <cstdint>
#include <cmath>

#define NB 16384          // batch
#define ND 1024           // V == H == 1024
#define KSTEPS 25

// ---------------- scratch (static __device__, no allocations) ----------------
__device__ float g_bmod[NB * ND];
__device__ float g_cmod[NB * ND];
__device__ float g_v[NB * ND];
__device__ float g_h[NB * ND];
__device__ float g_WT[ND * ND];
__device__ float g_fed[NB * 8];
__device__ float g_fem[NB * 8];
__device__ float g_rowacc[NB];

// ---------------- threefry2x32 (JAX-compatible, 20 rounds) ----------------
__device__ __forceinline__ void tf2x32(uint32_t k0, uint32_t k1, uint32_t x0, uint32_t x1,
                                       uint32_t &o0, uint32_t &o1) {
    uint32_t k2 = k0 ^ k1 ^ 0x1BD11BDAu;
    x0 += k0; x1 += k1;
#define TFR(r) { x0 += x1; x1 = __funnelshift_l(x1, x1, (r)); x1 ^= x0; }
    TFR(13) TFR(15) TFR(26) TFR(6)
    x0 += k1; x1 += k2 + 1u;
    TFR(17) TFR(29) TFR(16) TFR(24)
    x0 += k2; x1 += k0 + 2u;
    TFR(13) TFR(15) TFR(26) TFR(6)
    x0 += k0; x1 += k1 + 3u;
    TFR(17) TFR(29) TFR(16) TFR(24)
    x0 += k1; x1 += k2 + 4u;
    TFR(13) TFR(15) TFR(26) TFR(6)
    x0 += k2; x1 += k0 + 5u;
#undef TFR
    o0 = x0; o1 = x1;
}

// JAX partitionable 32-bit random bits: counter = (hi=0, lo=idx), bits = out0 ^ out1,
// uniform = bitcast(bits>>9 | 0x3f800000) - 1
__device__ __forceinline__ float uniform_from(uint32_t k0, uint32_t k1, uint32_t idx) {
    uint32_t o0, o1;
    tf2x32(k0, k1, 0u, idx, o0, o1);
    uint32_t bits = o0 ^ o1;
    return __uint_as_float((bits >> 9) | 0x3f800000u) - 1.0f;
}

// ---------------- small kernels ----------------
__global__ void init_v_k(float* __restrict__ v, uint32_t k0, uint32_t k1) {
    uint32_t j = blockIdx.x * 256u + threadIdx.x;
    float u = uniform_from(k0, k1, j);
    v[j] = (u < 0.5f) ? 1.0f : 0.0f;
}

__global__ void transpose_k(const float* __restrict__ W, float* __restrict__ WT) {
    __shared__ float t[32][33];
    int bx = blockIdx.x * 32, by = blockIdx.y * 32;
    int x = bx + threadIdx.x;
#pragma unroll
    for (int dy = 0; dy < 32; dy += 8)
        t[threadIdx.y + dy][threadIdx.x] = W[(by + threadIdx.y + dy) * ND + x];
    __syncthreads();
    int x2 = by + threadIdx.x;
#pragma unroll
    for (int dy = 0; dy < 32; dy += 8)
        WT[(bx + threadIdx.y + dy) * ND + x2] = t[threadIdx.x][threadIdx.y + dy];
}

// MLP: hidden = tanh(cond @ W1 + b1); params = hidden @ W2 + b2; build b_mod/c_mod.
__global__ void __launch_bounds__(256) mlp_mod_k(
    const float* __restrict__ cond, const float* __restrict__ W1, const float* __restrict__ b1,
    const float* __restrict__ W2, const float* __restrict__ b2,
    const float* __restrict__ b, const float* __restrict__ c,
    float* __restrict__ bmod, float* __restrict__ cmod)
{
    __shared__ float cond_s[32 * 64];
    __shared__ float W1_s[64 * 64];
    __shared__ float hid_s[32 * 64];
    int tid = threadIdx.x;
    int rowBase = blockIdx.x * 32;
    for (int idx = tid; idx < 2048; idx += 256) {
        int r = idx >> 6, i = idx & 63;
        cond_s[idx] = cond[(rowBase + r) * 64 + i];
    }
    for (int idx = tid; idx < 4096; idx += 256) W1_s[idx] = W1[idx];
    __syncthreads();
    for (int idx = tid; idx < 2048; idx += 256) {
        int r = idx >> 6, t = idx & 63;
        float a = b1[t];
#pragma unroll 16
        for (int i = 0; i < 64; i++) a += cond_s[r * 64 + i] * W1_s[i * 64 + t];
        hid_s[idx] = tanhf(a);
    }
    __syncthreads();
#pragma unroll 1
    for (int chunk = 0; chunk < 4; chunk++) {
        int v = chunk * 256 + tid;       // 0..1023
        float bv = b[v];
        float cv = c[v];
#pragma unroll 1
        for (int r = 0; r < 32; r++) {
            float gb = b2[v], bb = b2[ND + v];
            float gc = b2[2 * ND + v], bc2 = b2[3 * ND + v];
#pragma unroll 8
            for (int i = 0; i < 64; i++) {
                float hv = hid_s[r * 64 + i];
                const float* w2i = W2 + i * 4096;
                gb  += hv * w2i[v];
                bb  += hv * w2i[ND + v];
                gc  += hv * w2i[2 * ND + v];
                bc2 += hv * w2i[3 * ND + v];
            }
            bmod[(rowBase + r) * ND + v] = (1.0f + gb) * bv + bb;
            cmod[(rowBase + r) * ND + v] = (1.0f + gc) * cv + bc2;
        }
    }
}

// ---------------- fused GEMM (16384 x 1024 x 1024) ----------------
// MODE 0: out = bernoulli(sigmoid(A@B + mod), key)  [binary float]
// MODE 1: febuf[row][tileN] = sum_cols softplus(A@B + mod)
template<int MODE>
__global__ void __launch_bounds__(256, 2)
gemm_k(const float* __restrict__ A, const float* __restrict__ Bm,
       const float* __restrict__ mod, float* __restrict__ out,
       float* __restrict__ febuf, uint32_t k0, uint32_t k1)
{
    __shared__ float As[8][128];
    __shared__ float Bs[8][128];
    __shared__ float red[2048];

    const int tid = threadIdx.x;
    const int tx = tid & 15, ty = tid >> 4;
    const int rowBase = blockIdx.y * 128;
    const int colBase = blockIdx.x * 128;

    const int ar = tid >> 1;
    const int ak = (tid & 1) * 4;
    const int br = tid >> 5;
    const int bc = (tid & 31) * 4;

    const float* Ap = A + (rowBase + ar) * 1024 + ak;
    const float* Bp = Bm + br * 1024 + colBase + bc;

    float acc[8][8];
#pragma unroll
    for (int i = 0; i < 8; i++)
#pragma unroll
        for (int j = 0; j < 8; j++) acc[i][j] = 0.0f;

    float4 a4 = *(const float4*)Ap;
    float4 b4 = *(const float4*)Bp;

#pragma unroll 1
    for (int kt = 0; kt < 128; kt++) {
        As[ak + 0][ar] = a4.x; As[ak + 1][ar] = a4.y;
        As[ak + 2][ar] = a4.z; As[ak + 3][ar] = a4.w;
        *(float4*)(&Bs[br][bc]) = b4;
        __syncthreads();
        if (kt < 127) {
            a4 = *(const float4*)(Ap + (kt + 1) * 8);
            b4 = *(const float4*)(Bp + (kt + 1) * 8192);
        }
#pragma unroll
        for (int kk = 0; kk < 8; kk++) {
            float af[8], bf[8];
            *(float4*)(af)     = *(const float4*)(&As[kk][ty * 8]);
            *(float4*)(af + 4) = *(const float4*)(&As[kk][ty * 8 + 4]);
            *(float4*)(bf)     = *(const float4*)(&Bs[kk][tx * 8]);
            *(float4*)(bf + 4) = *(const float4*)(&Bs[kk][tx * 8 + 4]);
#pragma unroll
            for (int i = 0; i < 8; i++)
#pragma unroll
                for (int j = 0; j < 8; j++)
                    acc[i][j] += af[i] * bf[j];
        }
        __syncthreads();
    }

    if (MODE == 0) {
#pragma unroll
        for (int i = 0; i < 8; i++) {
            int r = rowBase + ty * 8 + i;
#pragma unroll
            for (int jc = 0; jc < 2; jc++) {
                int cb = colBase + tx * 8 + jc * 4;
                float4 m4 = *(const float4*)(mod + r * 1024 + cb);
                float mv[4] = {m4.x, m4.y, m4.z, m4.w};
                float ov[4];
#pragma unroll
                for (int q = 0; q < 4; q++) {
                    float pre = acc[i][jc * 4 + q] + mv[q];
                    float p = 1.0f / (1.0f + expf(-pre));
                    float u = uniform_from(k0, k1, (uint32_t)(r * 1024 + cb + q));
                    ov[q] = (u < p) ? 1.0f : 0.0f;
                }
                float4 o4; o4.x = ov[0]; o4.y = ov[1]; o4.z = ov[2]; o4.w = ov[3];
                *(float4*)(out + r * 1024 + cb) = o4;
            }
        }
    } else {
#pragma unroll
        for (int i = 0; i < 8; i++) {
            int r = rowBase + ty * 8 + i;
            float rs = 0.0f;
#pragma unroll
            for (int jc = 0; jc < 2; jc++) {
                int cb = colBase + tx * 8 + jc * 4;
                float4 m4 = *(const float4*)(mod + r * 1024 + cb);
                float mv[4] = {m4.x, m4.y, m4.z, m4.w};
#pragma unroll
                for (int q = 0; q < 4; q++) {
                    float pre = acc[i][jc * 4 + q] + mv[q];
                    rs += fmaxf(pre, 0.0f) + log1pf(expf(-fabsf(pre)));
                }
            }
            red[(ty * 8 + i) * 16 + tx] = rs;
        }
        __syncthreads();
        if (tid < 128) {
            float s = 0.0f;
#pragma unroll
            for (int t = 0; t < 16; t++) s += red[tid * 16 + t];
            febuf[(rowBase + tid) * 8 + blockIdx.x] = s;
        }
    }
}

// rowacc[r] = sum_c (vm - vd) * b_mod   (== dot_m - dot_d)
__global__ void dot_bmod_k(const float* __restrict__ vd, const float* __restrict__ vm,
                           const float* __restrict__ bmod, float* __restrict__ rowacc)
{
    int row = blockIdx.x * 8 + (threadIdx.x >> 5);
    int lane = threadIdx.x & 31;
    const float* pd = vd + row * ND;
    const float* pm = vm + row * ND;
    const float* pb = bmod + row * ND;
    float s = 0.0f;
    for (int c0 = lane; c0 < ND; c0 += 32)
        s += (pm[c0] - pd[c0]) * pb[c0];
#pragma unroll
    for (int off = 16; off > 0; off >>= 1) s += __shfl_down_sync(0xffffffffu, s, off);
    if (lane == 0) rowacc[row] = s;
}

// loss = mean_r [ rowacc[r] + sum_t fem[r][t] - sum_t fed[r][t] ]
__global__ void finalize_k(const float* __restrict__ rowacc, const float* __restrict__ fed,
                           const float* __restrict__ fem, float* __restrict__ outp)
{
    __shared__ float sm[256];
    float s = 0.0f;
    for (int r = threadIdx.x; r < NB; r += 256) {
        float t = rowacc[r];
#pragma unroll
        for (int q = 0; q < 8; q++) t += fem[r * 8 + q] - fed[r * 8 + q];
        s += t;
    }
    sm[threadIdx.x] = s;
    __syncthreads();
    for (int off = 128; off > 0; off >>= 1) {
        if (threadIdx.x < off) sm[threadIdx.x] += sm[threadIdx.x + off];
        __syncthreads();
    }
    if (threadIdx.x == 0) outp[0] = sm[0] / (float)NB;
}

// ---------------- host threefry + key schedule ----------------
static inline uint32_t h_rotl(uint32_t x, int r) { return (x << r) | (x >> (32 - r)); }
static void h_tf(uint32_t k0, uint32_t k1, uint32_t x0, uint32_t x1, uint32_t &o0, uint32_t &o1) {
    uint32_t k2 = k0 ^ k1 ^ 0x1BD11BDAu;
    x0 += k0; x1 += k1;
    auto R = [&](int r) { x0 += x1; x1 = h_rotl(x1, r); x1 ^= x0; };
    R(13); R(15); R(26); R(6);  x0 += k1; x1 += k2 + 1u;
    R(17); R(29); R(16); R(24); x0 += k2; x1 += k0 + 2u;
    R(13); R(15); R(26); R(6);  x0 += k0; x1 += k1 + 3u;
    R(17); R(29); R(16); R(24); x0 += k1; x1 += k2 + 4u;
    R(13); R(15); R(26); R(6);  x0 += k2; x1 += k0 + 5u;
    o0 = x0; o1 = x1;
}

extern "C" void kernel_launch(void* const* d_in, const int* in_sizes, int n_in,
                              void* d_out, int out_size)
{
    const float* v_data = (const float*)d_in[0];
    const float* cond   = (const float*)d_in[1];
    const float* W      = (const float*)d_in[2];
    const float* b      = (const float*)d_in[3];
    const float* c      = (const float*)d_in[4];
    const float* W1     = (const float*)d_in[5];
    const float* b1     = (const float*)d_in[6];
    const float* W2     = (const float*)d_in[7];
    const float* b2     = (const float*)d_in[8];

    float *bmod, *cmod, *v, *h, *WT, *fed, *fem, *rowacc;
    cudaGetSymbolAddress((void**)&bmod,   g_bmod);
    cudaGetSymbolAddress((void**)&cmod,   g_cmod);
    cudaGetSymbolAddress((void**)&v,      g_v);
    cudaGetSymbolAddress((void**)&h,      g_h);
    cudaGetSymbolAddress((void**)&WT,     g_WT);
    cudaGetSymbolAddress((void**)&fed,    g_fed);
    cudaGetSymbolAddress((void**)&fem,    g_fem);
    cudaGetSymbolAddress((void**)&rowacc, g_rowacc);

    transpose_k<<<dim3(32, 32), dim3(32, 8)>>>(W, WT);
    mlp_mod_k<<<512, 256>>>(cond, W1, b1, W2, b2, b, c, bmod, cmod);

    // key schedule: key(42) = (0,42); fold-like split: child_i = threefry(key, (0, i))
    uint32_t kc0, kc1, ks0, ks1;
    h_tf(0u, 42u, 0u, 0u, kc0, kc1);   // k_chain
    h_tf(0u, 42u, 0u, 1u, ks0, ks1);   // k_start

    init_v_k<<<(NB * ND) / 256, 256>>>(v, ks0, ks1);

    for (int s = 0; s < KSTEPS; s++) {
        uint32_t nk0, nk1, kh0, kh1, kv0, kv1;
        h_tf(kc0, kc1, 0u, 0u, nk0, nk1);   // new k
        h_tf(kc0, kc1, 0u, 1u, kh0, kh1);   // kh
        h_tf(kc0, kc1, 0u, 2u, kv0, kv1);   // kv
        kc0 = nk0; kc1 = nk1;
        gemm_k<0><<<dim3(8, 128), 256>>>(v, W,  cmod, h, nullptr, kh0, kh1);
        gemm_k<0><<<dim3(8, 128), 256>>>(h, WT, bmod, v, nullptr, kv0, kv1);
    }

    gemm_k<1><<<dim3(8, 128), 256>>>(v_data, W, cmod, nullptr, fed, 0u, 0u);
    gemm_k<1><<<dim3(8, 128), 256>>>(v,      W, cmod, nullptr, fem, 0u, 0u);
    dot_bmod_k<<<NB / 8, 256>>>(v_data, v, bmod, rowacc);
    finalize_k<<<1, 256>>>(rowacc, fed, fem, (float*)d_out);
}

// round 9
// speedup vs baseline: 2.9543x; 2.9543x over previous
#include <cuda_runtime.h>
#include <cuda_bf16.h>
#include <cstdint>
#include <cmath>

#define NB 16384          // batch
#define ND 1024           // V == H == 1024
#define KSTEPS 25

// ---------------- scratch (static __device__, no allocations) ----------------
__device__ float g_bmod[NB * ND];
__device__ float g_cmod[NB * ND];
__device__ __nv_bfloat16 g_v[NB * ND];
__device__ __nv_bfloat16 g_h[NB * ND];
__device__ __nv_bfloat16 g_vd[NB * ND];
__device__ __nv_bfloat16 g_Whi[ND * ND];
__device__ __nv_bfloat16 g_Wlo[ND * ND];
__device__ __nv_bfloat16 g_WThi[ND * ND];
__device__ __nv_bfloat16 g_WTlo[ND * ND];
__device__ float g_fed[NB * 16];
__device__ float g_fem[NB * 16];
__device__ float g_rowacc[NB];

// ---------------- ptx helpers (sm_80-compatible only — no tcgen05!) ----------------
__device__ __forceinline__ uint32_t smem_to_u32(const void* p) {
    uint32_t a;
    asm("{ .reg .u64 t; cvta.to.shared.u64 t, %1; cvt.u32.u64 %0, t; }" : "=r"(a) : "l"(p));
    return a;
}

#define CP_ASYNC16(dst, src) \
    asm volatile("cp.async.cg.shared.global [%0], [%1], 16;" :: "r"((uint32_t)(dst)), "l"(src) : "memory")
#define CP_COMMIT() asm volatile("cp.async.commit_group;" ::: "memory")
#define CP_WAIT(n)  asm volatile("cp.async.wait_group %0;" :: "n"(n) : "memory")

#define LDSM_X4(r, addr) \
    asm volatile("ldmatrix.sync.aligned.m8n8.x4.shared.b16 {%0,%1,%2,%3}, [%4];" \
        : "=r"((r)[0]), "=r"((r)[1]), "=r"((r)[2]), "=r"((r)[3]) : "r"((uint32_t)(addr)))

#define MMA16816(d, a, b0, b1) \
    asm volatile("mma.sync.aligned.m16n8k16.row.col.f32.bf16.bf16.f32 " \
        "{%0,%1,%2,%3}, {%4,%5,%6,%7}, {%8,%9}, {%0,%1,%2,%3};" \
        : "+f"((d)[0]), "+f"((d)[1]), "+f"((d)[2]), "+f"((d)[3]) \
        : "r"((a)[0]), "r"((a)[1]), "r"((a)[2]), "r"((a)[3]), "r"(b0), "r"(b1))

// ---------------- threefry2x32 (JAX-compatible, 20 rounds) ----------------
__device__ __forceinline__ void tf2x32(uint32_t k0, uint32_t k1, uint32_t x0, uint32_t x1,
                                       uint32_t &o0, uint32_t &o1) {
    uint32_t k2 = k0 ^ k1 ^ 0x1BD11BDAu;
    x0 += k0; x1 += k1;
#define TFR(r) { x0 += x1; x1 = __funnelshift_l(x1, x1, (r)); x1 ^= x0; }
    TFR(13) TFR(15) TFR(26) TFR(6)
    x0 += k1; x1 += k2 + 1u;
    TFR(17) TFR(29) TFR(16) TFR(24)
    x0 += k2; x1 += k0 + 2u;
    TFR(13) TFR(15) TFR(26) TFR(6)
    x0 += k0; x1 += k1 + 3u;
    TFR(17) TFR(29) TFR(16) TFR(24)
    x0 += k1; x1 += k2 + 4u;
    TFR(13) TFR(15) TFR(26) TFR(6)
    x0 += k2; x1 += k0 + 5u;
#undef TFR
    o0 = x0; o1 = x1;
}

__device__ __forceinline__ float uniform_from(uint32_t k0, uint32_t k1, uint32_t idx) {
    uint32_t o0, o1;
    tf2x32(k0, k1, 0u, idx, o0, o1);
    uint32_t bits = o0 ^ o1;
    return __uint_as_float((bits >> 9) | 0x3f800000u) - 1.0f;
}

// ---------------- small kernels ----------------
__global__ void init_v_k(__nv_bfloat16* __restrict__ v, uint32_t k0, uint32_t k1) {
    uint32_t j = blockIdx.x * 256u + threadIdx.x;
    float u = uniform_from(k0, k1, j);
    v[j] = __float2bfloat16((u < 0.5f) ? 1.0f : 0.0f);
}

__global__ void conv_bf16_k(const float* __restrict__ in, __nv_bfloat16* __restrict__ out) {
    uint32_t j = blockIdx.x * 256u + threadIdx.x;
    out[j] = __float2bfloat16(in[j]);
}

// W -> (hi, lo) bf16 split, plus transposed copies.
__global__ void split_w_k(const float* __restrict__ W,
                          __nv_bfloat16* __restrict__ Whi, __nv_bfloat16* __restrict__ Wlo,
                          __nv_bfloat16* __restrict__ WThi, __nv_bfloat16* __restrict__ WTlo)
{
    __shared__ float th[32][33];
    __shared__ float tl[32][33];
    int bx = blockIdx.x * 32, by = blockIdx.y * 32;
    int tx = threadIdx.x, ty = threadIdx.y;
#pragma unroll
    for (int dy = 0; dy < 32; dy += 8) {
        float w = W[(size_t)(by + ty + dy) * ND + bx + tx];
        float hi = __bfloat162float(__float2bfloat16(w));
        float lo = w - hi;
        Whi[(size_t)(by + ty + dy) * ND + bx + tx] = __float2bfloat16(hi);
        Wlo[(size_t)(by + ty + dy) * ND + bx + tx] = __float2bfloat16(lo);
        th[ty + dy][tx] = hi;
        tl[ty + dy][tx] = lo;
    }
    __syncthreads();
#pragma unroll
    for (int dy = 0; dy < 32; dy += 8) {
        WThi[(size_t)(bx + ty + dy) * ND + by + tx] = __float2bfloat16(th[tx][ty + dy]);
        WTlo[(size_t)(bx + ty + dy) * ND + by + tx] = __float2bfloat16(tl[tx][ty + dy]);
    }
}

// MLP: hidden = tanh(cond @ W1 + b1); params = hidden @ W2 + b2; build b_mod/c_mod.
__global__ void __launch_bounds__(256) mlp_mod_k(
    const float* __restrict__ cond, const float* __restrict__ W1, const float* __restrict__ b1,
    const float* __restrict__ W2, const float* __restrict__ b2,
    const float* __restrict__ b, const float* __restrict__ c,
    float* __restrict__ bmod, float* __restrict__ cmod)
{
    __shared__ float cond_s[32 * 64];
    __shared__ float W1_s[64 * 64];
    __shared__ float hid_s[32 * 64];
    int tid = threadIdx.x;
    int rowBase = blockIdx.x * 32;
    for (int idx = tid; idx < 2048; idx += 256) {
        int r = idx >> 6, i = idx & 63;
        cond_s[idx] = cond[(rowBase + r) * 64 + i];
    }
    for (int idx = tid; idx < 4096; idx += 256) W1_s[idx] = W1[idx];
    __syncthreads();
    for (int idx = tid; idx < 2048; idx += 256) {
        int r = idx >> 6, t = idx & 63;
        float a = b1[t];
#pragma unroll 16
        for (int i = 0; i < 64; i++) a += cond_s[r * 64 + i] * W1_s[i * 64 + t];
        hid_s[idx] = tanhf(a);
    }
    __syncthreads();
#pragma unroll 1
    for (int chunk = 0; chunk < 4; chunk++) {
        int v = chunk * 256 + tid;
        float bv = b[v];
        float cv = c[v];
#pragma unroll 1
        for (int r = 0; r < 32; r++) {
            float gb = b2[v], bb = b2[ND + v];
            float gc = b2[2 * ND + v], bc2 = b2[3 * ND + v];
#pragma unroll 8
            for (int i = 0; i < 64; i++) {
                float hv = hid_s[r * 64 + i];
                const float* w2i = W2 + i * 4096;
                gb  += hv * w2i[v];
                bb  += hv * w2i[ND + v];
                gc  += hv * w2i[2 * ND + v];
                bc2 += hv * w2i[3 * ND + v];
            }
            bmod[(size_t)(rowBase + r) * ND + v] = (1.0f + gb) * bv + bb;
            cmod[(size_t)(rowBase + r) * ND + v] = (1.0f + gc) * cv + bc2;
        }
    }
}

// ---------------- HMMA fused GEMM (16384 x 1024 x 1024, split bf16) ----------------
// D = A @ (Bhi + Blo)^T, fp32 accum in registers (B stored [N,K] K-major).
// MODE 0: out = bernoulli(sigmoid(D + mod), key) as bf16
// MODE 1: febuf[row*16 + blockIdx.x*2 + warpN] = partial sum_cols softplus(D + mod)
//
// CTA: 256 threads (8 warps), tile 128x128, K chunk = 32 (double-buffered cp.async).
// Smem rows padded to 80B -> ldmatrix addresses distinct mod 128 (conflict-free).
#define ROWB 80
#define APLANE (128 * ROWB)          // 10240
#define STAGE_B (3 * APLANE)         // 30720
#define SMEM_DYN (2 * STAGE_B)       // 61440

template<int MODE>
__global__ void __launch_bounds__(256, 2)
gemm_mma(const __nv_bfloat16* __restrict__ A, const __nv_bfloat16* __restrict__ Bhi,
         const __nv_bfloat16* __restrict__ Blo, const float* __restrict__ mod,
         __nv_bfloat16* __restrict__ out, float* __restrict__ febuf,
         uint32_t k0, uint32_t k1)
{
    extern __shared__ char smem[];
    const uint32_t sb = smem_to_u32(smem);
    const int tid  = threadIdx.x;
    const int wid  = tid >> 5, lane = tid & 31;
    const int warpM = wid >> 1, warpN = wid & 1;
    const int rowBase = blockIdx.y * 128;
    const int colBase = blockIdx.x * 128;

    // ---- cp.async geometry: chunk ch = tid (+256): row = ch>>2 (+64), c = ch&3 ----
    const int lr = tid >> 2, lc = tid & 3;
    const __nv_bfloat16* Ag  = A   + (size_t)(rowBase + lr) * ND + lc * 8;
    const __nv_bfloat16* Bhg = Bhi + (size_t)(colBase + lr) * ND + lc * 8;
    const __nv_bfloat16* Blg = Blo + (size_t)(colBase + lr) * ND + lc * 8;
    const uint32_t s0 = (uint32_t)lr * ROWB + lc * 16;
    const uint32_t s1 = s0 + 64 * ROWB;

    // ---- ldmatrix lane bases ----
    // A (x4): lanes 0-15 -> row (lane&15), +0B ; lanes 16-31 -> row (lane&15), +16B
    const uint32_t offA = (uint32_t)(warpM * 32 + (lane & 15)) * ROWB + (lane >> 4) * 16;
    // B (x4): g=lane>>3: row rB + (g>>1)*8, byte + (g&1)*16
    const int rB = lane & 7, gB = lane >> 3;
    const uint32_t offB = (uint32_t)(warpN * 64 + (gB >> 1) * 8 + rB) * ROWB + (gB & 1) * 16;

    float acc[2][8][4];
#pragma unroll
    for (int mt = 0; mt < 2; mt++)
#pragma unroll
        for (int nt = 0; nt < 8; nt++)
#pragma unroll
            for (int e = 0; e < 4; e++) acc[mt][nt][e] = 0.0f;

    auto load_stage = [&](int kt, int stg) {
        uint32_t st = sb + stg * STAGE_B;
        size_t ko = (size_t)kt * 32;
        CP_ASYNC16(st + s0,              Ag  + ko);
        CP_ASYNC16(st + s1,              Ag  + 64 * ND + ko);
        CP_ASYNC16(st + APLANE + s0,     Bhg + ko);
        CP_ASYNC16(st + APLANE + s1,     Bhg + 64 * ND + ko);
        CP_ASYNC16(st + 2 * APLANE + s0, Blg + ko);
        CP_ASYNC16(st + 2 * APLANE + s1, Blg + 64 * ND + ko);
        CP_COMMIT();
    };

    load_stage(0, 0);
#pragma unroll 1
    for (int kt = 0; kt < 32; kt++) {
        const int buf = kt & 1;
        if (kt + 1 < 32) { load_stage(kt + 1, buf ^ 1); CP_WAIT(1); }
        else             { CP_WAIT(0); }
        __syncthreads();
        const uint32_t st = sb + buf * STAGE_B;
#pragma unroll
        for (int s = 0; s < 2; s++) {
            uint32_t a0[4], a1[4];
            LDSM_X4(a0, st + offA + s * 32);
            LDSM_X4(a1, st + offA + 16 * ROWB + s * 32);
#pragma unroll
            for (int pl = 0; pl < 2; pl++) {
                const uint32_t bbase = st + (1 + pl) * APLANE + offB + s * 32;
#pragma unroll
                for (int ntp = 0; ntp < 4; ntp++) {
                    uint32_t bb[4];
                    LDSM_X4(bb, bbase + ntp * 16 * ROWB);
                    MMA16816(acc[0][2 * ntp],     a0, bb[0], bb[1]);
                    MMA16816(acc[0][2 * ntp + 1], a0, bb[2], bb[3]);
                    MMA16816(acc[1][2 * ntp],     a1, bb[0], bb[1]);
                    MMA16816(acc[1][2 * ntp + 1], a1, bb[2], bb[3]);
                }
            }
        }
        __syncthreads();
    }

    // ---------------- epilogue ----------------
    const int q = lane >> 2, t = lane & 3;
    float rsum[2][2] = {{0.0f, 0.0f}, {0.0f, 0.0f}};
#pragma unroll
    for (int mt = 0; mt < 2; mt++) {
#pragma unroll
        for (int nt = 0; nt < 8; nt++) {
            const int col = colBase + warpN * 64 + nt * 8 + 2 * t;
#pragma unroll
            for (int hh = 0; hh < 2; hh++) {
                const int r = rowBase + warpM * 32 + mt * 16 + q + hh * 8;
                const uint32_t base = (uint32_t)r * (uint32_t)ND + (uint32_t)col;
                const float2 m2 = *reinterpret_cast<const float2*>(mod + base);
                const float pre0 = acc[mt][nt][2 * hh]     + m2.x;
                const float pre1 = acc[mt][nt][2 * hh + 1] + m2.y;
                if (MODE == 0) {
                    float p0 = 1.0f / (1.0f + expf(-pre0));
                    float p1 = 1.0f / (1.0f + expf(-pre1));
                    float u0 = uniform_from(k0, k1, base);
                    float u1 = uniform_from(k0, k1, base + 1u);
                    uint32_t pair = (u0 < p0 ? 0x3F80u : 0u) | ((u1 < p1 ? 0x3F80u : 0u) << 16);
                    *reinterpret_cast<uint32_t*>(out + base) = pair;
                } else {
                    rsum[mt][hh] += fmaxf(pre0, 0.0f) + log1pf(expf(-fabsf(pre0)))
                                  + fmaxf(pre1, 0.0f) + log1pf(expf(-fabsf(pre1)));
                }
            }
        }
    }
    if (MODE == 1) {
#pragma unroll
        for (int mt = 0; mt < 2; mt++)
#pragma unroll
            for (int hh = 0; hh < 2; hh++) {
                float v = rsum[mt][hh];
                v += __shfl_xor_sync(0xffffffffu, v, 1);
                v += __shfl_xor_sync(0xffffffffu, v, 2);
                if (t == 0) {
                    const int r = rowBase + warpM * 32 + mt * 16 + q + hh * 8;
                    febuf[(size_t)r * 16 + blockIdx.x * 2 + warpN] = v;
                }
            }
    }
}

// rowacc[r] = sum_c (vm - vd) * b_mod
__global__ void dot_bmod_k(const __nv_bfloat16* __restrict__ vd, const __nv_bfloat16* __restrict__ vm,
                           const float* __restrict__ bmod, float* __restrict__ rowacc)
{
    int row = blockIdx.x * 8 + (threadIdx.x >> 5);
    int lane = threadIdx.x & 31;
    const __nv_bfloat16* pd = vd + (size_t)row * ND;
    const __nv_bfloat16* pm = vm + (size_t)row * ND;
    const float* pb = bmod + (size_t)row * ND;
    float s = 0.0f;
    for (int c0 = lane; c0 < ND; c0 += 32)
        s += (__bfloat162float(pm[c0]) - __bfloat162float(pd[c0])) * pb[c0];
#pragma unroll
    for (int off = 16; off > 0; off >>= 1) s += __shfl_down_sync(0xffffffffu, s, off);
    if (lane == 0) rowacc[row] = s;
}

__global__ void finalize_k(const float* __restrict__ rowacc, const float* __restrict__ fed,
                           const float* __restrict__ fem, float* __restrict__ outp)
{
    __shared__ float sm[256];
    float s = 0.0f;
    for (int r = threadIdx.x; r < NB; r += 256) {
        float t = rowacc[r];
#pragma unroll
        for (int q = 0; q < 16; q++) t += fem[r * 16 + q] - fed[r * 16 + q];
        s += t;
    }
    sm[threadIdx.x] = s;
    __syncthreads();
    for (int off = 128; off > 0; off >>= 1) {
        if (threadIdx.x < off) sm[threadIdx.x] += sm[threadIdx.x + off];
        __syncthreads();
    }
    if (threadIdx.x == 0) outp[0] = sm[0] / (float)NB;
}

// ---------------- host threefry + key schedule ----------------
static inline uint32_t h_rotl(uint32_t x, int r) { return (x << r) | (x >> (32 - r)); }
static void h_tf(uint32_t k0, uint32_t k1, uint32_t x0, uint32_t x1, uint32_t &o0, uint32_t &o1) {
    uint32_t k2 = k0 ^ k1 ^ 0x1BD11BDAu;
    x0 += k0; x1 += k1;
    auto R = [&](int r) { x0 += x1; x1 = h_rotl(x1, r); x1 ^= x0; };
    R(13); R(15); R(26); R(6);  x0 += k1; x1 += k2 + 1u;
    R(17); R(29); R(16); R(24); x0 += k2; x1 += k0 + 2u;
    R(13); R(15); R(26); R(6);  x0 += k0; x1 += k1 + 3u;
    R(17); R(29); R(16); R(24); x0 += k1; x1 += k2 + 4u;
    R(13); R(15); R(26); R(6);  x0 += k2; x1 += k0 + 5u;
    o0 = x0; o1 = x1;
}

extern "C" void kernel_launch(void* const* d_in, const int* in_sizes, int n_in,
                              void* d_out, int out_size)
{
    const float* v_data = (const float*)d_in[0];
    const float* cond   = (const float*)d_in[1];
    const float* W      = (const float*)d_in[2];
    const float* b      = (const float*)d_in[3];
    const float* c      = (const float*)d_in[4];
    const float* W1     = (const float*)d_in[5];
    const float* b1     = (const float*)d_in[6];
    const float* W2     = (const float*)d_in[7];
    const float* b2     = (const float*)d_in[8];

    float *bmod, *cmod, *fed, *fem, *rowacc;
    __nv_bfloat16 *v, *h, *vd, *Whi, *Wlo, *WThi, *WTlo;
    cudaGetSymbolAddress((void**)&bmod,   g_bmod);
    cudaGetSymbolAddress((void**)&cmod,   g_cmod);
    cudaGetSymbolAddress((void**)&v,      g_v);
    cudaGetSymbolAddress((void**)&h,      g_h);
    cudaGetSymbolAddress((void**)&vd,     g_vd);
    cudaGetSymbolAddress((void**)&Whi,    g_Whi);
    cudaGetSymbolAddress((void**)&Wlo,    g_Wlo);
    cudaGetSymbolAddress((void**)&WThi,   g_WThi);
    cudaGetSymbolAddress((void**)&WTlo,   g_WTlo);
    cudaGetSymbolAddress((void**)&fed,    g_fed);
    cudaGetSymbolAddress((void**)&fem,    g_fem);
    cudaGetSymbolAddress((void**)&rowacc, g_rowacc);

    cudaFuncSetAttribute(gemm_mma<0>, cudaFuncAttributeMaxDynamicSharedMemorySize, SMEM_DYN);
    cudaFuncSetAttribute(gemm_mma<1>, cudaFuncAttributeMaxDynamicSharedMemorySize, SMEM_DYN);

    split_w_k<<<dim3(32, 32), dim3(32, 8)>>>(W, Whi, Wlo, WThi, WTlo);
    mlp_mod_k<<<512, 256>>>(cond, W1, b1, W2, b2, b, c, bmod, cmod);
    conv_bf16_k<<<(NB * ND) / 256, 256>>>(v_data, vd);

    // key schedule: key(42) = (0,42); fold-like split: child_i = threefry(key, (0, i))
    uint32_t kc0, kc1, ks0, ks1;
    h_tf(0u, 42u, 0u, 0u, kc0, kc1);   // k_chain
    h_tf(0u, 42u, 0u, 1u, ks0, ks1);   // k_start

    init_v_k<<<(NB * ND) / 256, 256>>>(v, ks0, ks1);

    for (int s = 0; s < KSTEPS; s++) {
        uint32_t nk0, nk1, kh0, kh1, kv0, kv1;
        h_tf(kc0, kc1, 0u, 0u, nk0, nk1);
        h_tf(kc0, kc1, 0u, 1u, kh0, kh1);
        h_tf(kc0, kc1, 0u, 2u, kv0, kv1);
        kc0 = nk0; kc1 = nk1;
        // h = bern(sigmoid(v @ W + cmod)):  B[n][k] = W[k][n] -> WT planes
        gemm_mma<0><<<dim3(8, 128), 256, SMEM_DYN>>>(v, WThi, WTlo, cmod, h, nullptr, kh0, kh1);
        // v = bern(sigmoid(h @ W^T + bmod)): B[n][k] = W[n][k] -> W planes
        gemm_mma<0><<<dim3(8, 128), 256, SMEM_DYN>>>(h, Whi, Wlo, bmod, v, nullptr, kv0, kv1);
    }

    gemm_mma<1><<<dim3(8, 128), 256, SMEM_DYN>>>(vd, WThi, WTlo, cmod, nullptr, fed, 0u, 0u);
    gemm_mma<1><<<dim3(8, 128), 256, SMEM_DYN>>>(v,  WThi, WTlo, cmod, nullptr, fem, 0u, 0u);
    dot_bmod_k<<<NB / 8, 256>>>(vd, v, bmod, rowacc);
    finalize_k<<<1, 256>>>(rowacc, fed, fem, (float*)d_out);
}

// round 12
// speedup vs baseline: 4.2018x; 1.4223x over previous
#include <cuda_runtime.h>
#include <cuda_bf16.h>
#include <cstdint>
#include <cmath>

#define NB 16384          // batch
#define ND 1024           // V == H == 1024
#define KSTEPS 25

// ---------------- scratch (static __device__, no allocations) ----------------
__device__ float g_bmod[NB * ND];
__device__ float g_cmod[NB * ND];
__device__ __nv_bfloat16 g_v[NB * ND];
__device__ __nv_bfloat16 g_h[NB * ND];
__device__ __nv_bfloat16 g_vd[NB * ND];
__device__ __nv_bfloat16 g_Whi[ND * ND];
__device__ __nv_bfloat16 g_Wlo[ND * ND];
__device__ __nv_bfloat16 g_WThi[ND * ND];
__device__ __nv_bfloat16 g_WTlo[ND * ND];
__device__ float g_fed[NB * 16];
__device__ float g_fem[NB * 16];
__device__ float g_rowacc[NB];

// ---------------- ptx helpers (sm_80-compatible only — no tcgen05!) ----------------
__device__ __forceinline__ uint32_t smem_to_u32(const void* p) {
    uint32_t a;
    asm("{ .reg .u64 t; cvta.to.shared.u64 t, %1; cvt.u32.u64 %0, t; }" : "=r"(a) : "l"(p));
    return a;
}

#define CP_ASYNC16(dst, src) \
    asm volatile("cp.async.cg.shared.global [%0], [%1], 16;" :: "r"((uint32_t)(dst)), "l"(src) : "memory")
#define CP_COMMIT() asm volatile("cp.async.commit_group;" ::: "memory")
#define CP_WAIT(n)  asm volatile("cp.async.wait_group %0;" :: "n"(n) : "memory")

#define LDSM_X4(r, addr) \
    asm volatile("ldmatrix.sync.aligned.m8n8.x4.shared.b16 {%0,%1,%2,%3}, [%4];" \
        : "=r"((r)[0]), "=r"((r)[1]), "=r"((r)[2]), "=r"((r)[3]) : "r"((uint32_t)(addr)))

#define MMA16816(d, a, b0, b1) \
    asm volatile("mma.sync.aligned.m16n8k16.row.col.f32.bf16.bf16.f32 " \
        "{%0,%1,%2,%3}, {%4,%5,%6,%7}, {%8,%9}, {%0,%1,%2,%3};" \
        : "+f"((d)[0]), "+f"((d)[1]), "+f"((d)[2]), "+f"((d)[3]) \
        : "r"((a)[0]), "r"((a)[1]), "r"((a)[2]), "r"((a)[3]), "r"(b0), "r"(b1))

// ---------------- threefry2x32 (JAX-compatible, 20 rounds) ----------------
__device__ __forceinline__ void tf2x32(uint32_t k0, uint32_t k1, uint32_t x0, uint32_t x1,
                                       uint32_t &o0, uint32_t &o1) {
    uint32_t k2 = k0 ^ k1 ^ 0x1BD11BDAu;
    x0 += k0; x1 += k1;
#define TFR(r) { x0 += x1; x1 = __funnelshift_l(x1, x1, (r)); x1 ^= x0; }
    TFR(13) TFR(15) TFR(26) TFR(6)
    x0 += k1; x1 += k2 + 1u;
    TFR(17) TFR(29) TFR(16) TFR(24)
    x0 += k2; x1 += k0 + 2u;
    TFR(13) TFR(15) TFR(26) TFR(6)
    x0 += k0; x1 += k1 + 3u;
    TFR(17) TFR(29) TFR(16) TFR(24)
    x0 += k1; x1 += k2 + 4u;
    TFR(13) TFR(15) TFR(26) TFR(6)
    x0 += k2; x1 += k0 + 5u;
#undef TFR
    o0 = x0; o1 = x1;
}

__device__ __forceinline__ float uniform_from(uint32_t k0, uint32_t k1, uint32_t idx) {
    uint32_t o0, o1;
    tf2x32(k0, k1, 0u, idx, o0, o1);
    uint32_t bits = o0 ^ o1;
    return __uint_as_float((bits >> 9) | 0x3f800000u) - 1.0f;
}

// ---------------- small kernels ----------------
// fused: vd = bf16(v_data); v = bernoulli(0.5) start state
__global__ void init_conv_k(const float* __restrict__ v_data, __nv_bfloat16* __restrict__ vd,
                            __nv_bfloat16* __restrict__ v, uint32_t k0, uint32_t k1) {
    uint32_t j = blockIdx.x * 256u + threadIdx.x;
    vd[j] = __float2bfloat16(v_data[j]);
    float u = uniform_from(k0, k1, j);
    v[j] = __float2bfloat16((u < 0.5f) ? 1.0f : 0.0f);
}

// W -> (hi, lo) bf16 split, plus transposed copies.
__global__ void split_w_k(const float* __restrict__ W,
                          __nv_bfloat16* __restrict__ Whi, __nv_bfloat16* __restrict__ Wlo,
                          __nv_bfloat16* __restrict__ WThi, __nv_bfloat16* __restrict__ WTlo)
{
    __shared__ float th[32][33];
    __shared__ float tl[32][33];
    int bx = blockIdx.x * 32, by = blockIdx.y * 32;
    int tx = threadIdx.x, ty = threadIdx.y;
#pragma unroll
    for (int dy = 0; dy < 32; dy += 8) {
        float w = W[(size_t)(by + ty + dy) * ND + bx + tx];
        float hi = __bfloat162float(__float2bfloat16(w));
        float lo = w - hi;
        Whi[(size_t)(by + ty + dy) * ND + bx + tx] = __float2bfloat16(hi);
        Wlo[(size_t)(by + ty + dy) * ND + bx + tx] = __float2bfloat16(lo);
        th[ty + dy][tx] = hi;
        tl[ty + dy][tx] = lo;
    }
    __syncthreads();
#pragma unroll
    for (int dy = 0; dy < 32; dy += 8) {
        WThi[(size_t)(bx + ty + dy) * ND + by + tx] = __float2bfloat16(th[tx][ty + dy]);
        WTlo[(size_t)(bx + ty + dy) * ND + by + tx] = __float2bfloat16(tl[tx][ty + dy]);
    }
}

// MLP: hidden = tanh(cond @ W1 + b1); params = hidden @ W2 + b2; build b_mod/c_mod.
__global__ void __launch_bounds__(256) mlp_mod_k(
    const float* __restrict__ cond, const float* __restrict__ W1, const float* __restrict__ b1,
    const float* __restrict__ W2, const float* __restrict__ b2,
    const float* __restrict__ b, const float* __restrict__ c,
    float* __restrict__ bmod, float* __restrict__ cmod)
{
    __shared__ float cond_s[32 * 64];
    __shared__ float W1_s[64 * 64];
    __shared__ float hid_s[32 * 64];
    int tid = threadIdx.x;
    int rowBase = blockIdx.x * 32;
    for (int idx = tid; idx < 2048; idx += 256) {
        int r = idx >> 6, i = idx & 63;
        cond_s[idx] = cond[(rowBase + r) * 64 + i];
    }
    for (int idx = tid; idx < 4096; idx += 256) W1_s[idx] = W1[idx];
    __syncthreads();
    for (int idx = tid; idx < 2048; idx += 256) {
        int r = idx >> 6, t = idx & 63;
        float a = b1[t];
#pragma unroll 16
        for (int i = 0; i < 64; i++) a += cond_s[r * 64 + i] * W1_s[i * 64 + t];
        hid_s[idx] = tanhf(a);
    }
    __syncthreads();
#pragma unroll 1
    for (int chunk = 0; chunk < 4; chunk++) {
        int v = chunk * 256 + tid;
        float bv = b[v];
        float cv = c[v];
#pragma unroll 1
        for (int r = 0; r < 32; r++) {
            float gb = b2[v], bb = b2[ND + v];
            float gc = b2[2 * ND + v], bc2 = b2[3 * ND + v];
#pragma unroll 8
            for (int i = 0; i < 64; i++) {
                float hv = hid_s[r * 64 + i];
                const float* w2i = W2 + i * 4096;
                gb  += hv * w2i[v];
                bb  += hv * w2i[ND + v];
                gc  += hv * w2i[2 * ND + v];
                bc2 += hv * w2i[3 * ND + v];
            }
            bmod[(size_t)(rowBase + r) * ND + v] = (1.0f + gb) * bv + bb;
            cmod[(size_t)(rowBase + r) * ND + v] = (1.0f + gc) * cv + bc2;
        }
    }
}

// ---------------- HMMA fused GEMM (16384 x 1024 x 1024) ----------------
// D = A @ B^T (PLANES=1: B=Bhi; PLANES=2: B=Bhi+Blo), fp32 accum (B stored [N,K] K-major).
// MODE 0: out = bernoulli(sigmoid(D + mod), key) as bf16
// MODE 1: febuf[row*16 + blockIdx.x*2 + warpN] = partial sum_cols softplus(D + mod)
//
// CTA: 256 threads (8 warps), tile 128x128, K chunk = 32, STAGES-deep cp.async ring,
// one __syncthreads per chunk. Smem rows padded to 80B (conflict-free ldmatrix).
#define ROWB 80
#define APLANE (128 * ROWB)          // 10240

template<int MODE, int PLANES, int STAGES>
__global__ void __launch_bounds__(256, 2)
gemm_mma(const __nv_bfloat16* __restrict__ A, const __nv_bfloat16* __restrict__ Bhi,
         const __nv_bfloat16* __restrict__ Blo, const float* __restrict__ mod,
         __nv_bfloat16* __restrict__ out, float* __restrict__ febuf,
         uint32_t k0, uint32_t k1)
{
    constexpr int STAGE_B = (1 + PLANES) * APLANE;
    extern __shared__ char smem[];
    const uint32_t sb = smem_to_u32(smem);
    const int tid  = threadIdx.x;
    const int wid  = tid >> 5, lane = tid & 31;
    const int warpM = wid >> 1, warpN = wid & 1;
    const int rowBase = blockIdx.y * 128;
    const int colBase = blockIdx.x * 128;

    // ---- cp.async geometry ----
    const int lr = tid >> 2, lc = tid & 3;
    const __nv_bfloat16* Ag  = A   + (size_t)(rowBase + lr) * ND + lc * 8;
    const __nv_bfloat16* Bhg = Bhi + (size_t)(colBase + lr) * ND + lc * 8;
    const __nv_bfloat16* Blg = (PLANES == 2) ? (Blo + (size_t)(colBase + lr) * ND + lc * 8) : nullptr;
    const uint32_t s0 = (uint32_t)lr * ROWB + lc * 16;
    const uint32_t s1 = s0 + 64 * ROWB;

    // ---- ldmatrix lane bases ----
    const uint32_t offA = (uint32_t)(warpM * 32 + (lane & 15)) * ROWB + (lane >> 4) * 16;
    const int rB = lane & 7, gB = lane >> 3;
    const uint32_t offB = (uint32_t)(warpN * 64 + (gB >> 1) * 8 + rB) * ROWB + (gB & 1) * 16;

    float acc[2][8][4];
#pragma unroll
    for (int mt = 0; mt < 2; mt++)
#pragma unroll
        for (int nt = 0; nt < 8; nt++)
#pragma unroll
            for (int e = 0; e < 4; e++) acc[mt][nt][e] = 0.0f;

    auto load_stage = [&](int kt, int stg) {
        uint32_t st = sb + stg * STAGE_B;
        size_t ko = (size_t)kt * 32;
        CP_ASYNC16(st + s0,          Ag  + ko);
        CP_ASYNC16(st + s1,          Ag  + 64 * ND + ko);
        CP_ASYNC16(st + APLANE + s0, Bhg + ko);
        CP_ASYNC16(st + APLANE + s1, Bhg + 64 * ND + ko);
        if (PLANES == 2) {
            CP_ASYNC16(st + 2 * APLANE + s0, Blg + ko);
            CP_ASYNC16(st + 2 * APLANE + s1, Blg + 64 * ND + ko);
        }
        CP_COMMIT();
    };

#pragma unroll
    for (int p = 0; p < STAGES - 1; p++) load_stage(p, p);

#pragma unroll 1
    for (int kt = 0; kt < 32; kt++) {
        CP_WAIT(STAGES - 2);
        __syncthreads();
        if (kt + STAGES - 1 < 32) load_stage(kt + STAGES - 1, (kt + STAGES - 1) % STAGES);
        else                      CP_COMMIT();   // dummy group keeps wait arithmetic uniform
        const uint32_t st = sb + (kt % STAGES) * STAGE_B;
#pragma unroll
        for (int s = 0; s < 2; s++) {
            uint32_t a0[4], a1[4];
            LDSM_X4(a0, st + offA + s * 32);
            LDSM_X4(a1, st + offA + 16 * ROWB + s * 32);
#pragma unroll
            for (int pl = 0; pl < PLANES; pl++) {
                const uint32_t bbase = st + (1 + pl) * APLANE + offB + s * 32;
#pragma unroll
                for (int ntp = 0; ntp < 4; ntp++) {
                    uint32_t bb[4];
                    LDSM_X4(bb, bbase + ntp * 16 * ROWB);
                    MMA16816(acc[0][2 * ntp],     a0, bb[0], bb[1]);
                    MMA16816(acc[0][2 * ntp + 1], a0, bb[2], bb[3]);
                    MMA16816(acc[1][2 * ntp],     a1, bb[0], bb[1]);
                    MMA16816(acc[1][2 * ntp + 1], a1, bb[2], bb[3]);
                }
            }
        }
    }

    // ---------------- epilogue ----------------
    const int q = lane >> 2, t = lane & 3;
    float rsum[2][2] = {{0.0f, 0.0f}, {0.0f, 0.0f}};
#pragma unroll
    for (int mt = 0; mt < 2; mt++) {
#pragma unroll
        for (int nt = 0; nt < 8; nt++) {
            const int col = colBase + warpN * 64 + nt * 8 + 2 * t;
#pragma unroll
            for (int hh = 0; hh < 2; hh++) {
                const int r = rowBase + warpM * 32 + mt * 16 + q + hh * 8;
                const uint32_t base = (uint32_t)r * (uint32_t)ND + (uint32_t)col;
                const float2 m2 = *reinterpret_cast<const float2*>(mod + base);
                const float pre0 = acc[mt][nt][2 * hh]     + m2.x;
                const float pre1 = acc[mt][nt][2 * hh + 1] + m2.y;
                if (MODE == 0) {
                    float p0 = 1.0f / (1.0f + expf(-pre0));
                    float p1 = 1.0f / (1.0f + expf(-pre1));
                    float u0 = uniform_from(k0, k1, base);
                    float u1 = uniform_from(k0, k1, base + 1u);
                    uint32_t pair = (u0 < p0 ? 0x3F80u : 0u) | ((u1 < p1 ? 0x3F80u : 0u) << 16);
                    *reinterpret_cast<uint32_t*>(out + base) = pair;
                } else {
                    rsum[mt][hh] += fmaxf(pre0, 0.0f) + log1pf(expf(-fabsf(pre0)))
                                  + fmaxf(pre1, 0.0f) + log1pf(expf(-fabsf(pre1)));
                }
            }
        }
    }
    if (MODE == 1) {
#pragma unroll
        for (int mt = 0; mt < 2; mt++)
#pragma unroll
            for (int hh = 0; hh < 2; hh++) {
                float v = rsum[mt][hh];
                v += __shfl_xor_sync(0xffffffffu, v, 1);
                v += __shfl_xor_sync(0xffffffffu, v, 2);
                if (t == 0) {
                    const int r = rowBase + warpM * 32 + mt * 16 + q + hh * 8;
                    febuf[(size_t)r * 16 + blockIdx.x * 2 + warpN] = v;
                }
            }
    }
}

// rowacc[r] = sum_c (vm - vd) * b_mod
__global__ void dot_bmod_k(const __nv_bfloat16* __restrict__ vd, const __nv_bfloat16* __restrict__ vm,
                           const float* __restrict__ bmod, float* __restrict__ rowacc)
{
    int row = blockIdx.x * 8 + (threadIdx.x >> 5);
    int lane = threadIdx.x & 31;
    const __nv_bfloat16* pd = vd + (size_t)row * ND;
    const __nv_bfloat16* pm = vm + (size_t)row * ND;
    const float* pb = bmod + (size_t)row * ND;
    float s = 0.0f;
    for (int c0 = lane; c0 < ND; c0 += 32)
        s += (__bfloat162float(pm[c0]) - __bfloat162float(pd[c0])) * pb[c0];
#pragma unroll
    for (int off = 16; off > 0; off >>= 1) s += __shfl_down_sync(0xffffffffu, s, off);
    if (lane == 0) rowacc[row] = s;
}

__global__ void finalize_k(const float* __restrict__ rowacc, const float* __restrict__ fed,
                           const float* __restrict__ fem, float* __restrict__ outp)
{
    __shared__ float sm[256];
    float s = 0.0f;
    for (int r = threadIdx.x; r < NB; r += 256) {
        float t = rowacc[r];
#pragma unroll
        for (int q = 0; q < 16; q++) t += fem[r * 16 + q] - fed[r * 16 + q];
        s += t;
    }
    sm[threadIdx.x] = s;
    __syncthreads();
    for (int off = 128; off > 0; off >>= 1) {
        if (threadIdx.x < off) sm[threadIdx.x] += sm[threadIdx.x + off];
        __syncthreads();
    }
    if (threadIdx.x == 0) outp[0] = sm[0] / (float)NB;
}

// ---------------- host threefry + key schedule ----------------
static inline uint32_t h_rotl(uint32_t x, int r) { return (x << r) | (x >> (32 - r)); }
static void h_tf(uint32_t k0, uint32_t k1, uint32_t x0, uint32_t x1, uint32_t &o0, uint32_t &o1) {
    uint32_t k2 = k0 ^ k1 ^ 0x1BD11BDAu;
    x0 += k0; x1 += k1;
    auto R = [&](int r) { x0 += x1; x1 = h_rotl(x1, r); x1 ^= x0; };
    R(13); R(15); R(26); R(6);  x0 += k1; x1 += k2 + 1u;
    R(17); R(29); R(16); R(24); x0 += k2; x1 += k0 + 2u;
    R(13); R(15); R(26); R(6);  x0 += k0; x1 += k1 + 3u;
    R(17); R(29); R(16); R(24); x0 += k1; x1 += k2 + 4u;
    R(13); R(15); R(26); R(6);  x0 += k2; x1 += k0 + 5u;
    o0 = x0; o1 = x1;
}

extern "C" void kernel_launch(void* const* d_in, const int* in_sizes, int n_in,
                              void* d_out, int out_size)
{
    const float* v_data = (const float*)d_in[0];
    const float* cond   = (const float*)d_in[1];
    const float* W      = (const float*)d_in[2];
    const float* b      = (const float*)d_in[3];
    const float* c      = (const float*)d_in[4];
    const float* W1     = (const float*)d_in[5];
    const float* b1     = (const float*)d_in[6];
    const float* W2     = (const float*)d_in[7];
    const float* b2     = (const float*)d_in[8];

    float *bmod, *cmod, *fed, *fem, *rowacc;
    __nv_bfloat16 *v, *h, *vd, *Whi, *Wlo, *WThi, *WTlo;
    cudaGetSymbolAddress((void**)&bmod,   g_bmod);
    cudaGetSymbolAddress((void**)&cmod,   g_cmod);
    cudaGetSymbolAddress((void**)&v,      g_v);
    cudaGetSymbolAddress((void**)&h,      g_h);
    cudaGetSymbolAddress((void**)&vd,     g_vd);
    cudaGetSymbolAddress((void**)&Whi,    g_Whi);
    cudaGetSymbolAddress((void**)&Wlo,    g_Wlo);
    cudaGetSymbolAddress((void**)&WThi,   g_WThi);
    cudaGetSymbolAddress((void**)&WTlo,   g_WTlo);
    cudaGetSymbolAddress((void**)&fed,    g_fed);
    cudaGetSymbolAddress((void**)&fem,    g_fem);
    cudaGetSymbolAddress((void**)&rowacc, g_rowacc);

    constexpr int SMEM_CHAIN = 4 * 2 * APLANE;  // 4 stages, A + 1 B plane  (81920)
    constexpr int SMEM_FE    = 2 * 3 * APLANE;  // 2 stages, A + 2 B planes (61440)
    cudaFuncSetAttribute((const void*)gemm_mma<0,1,4>, cudaFuncAttributeMaxDynamicSharedMemorySize, SMEM_CHAIN);
    cudaFuncSetAttribute((const void*)gemm_mma<1,2,2>, cudaFuncAttributeMaxDynamicSharedMemorySize, SMEM_FE);

    split_w_k<<<dim3(32, 32), dim3(32, 8)>>>(W, Whi, Wlo, WThi, WTlo);
    mlp_mod_k<<<512, 256>>>(cond, W1, b1, W2, b2, b, c, bmod, cmod);

    // key schedule: key(42) = (0,42); fold-like split: child_i = threefry(key, (0, i))
    uint32_t kc0, kc1, ks0, ks1;
    h_tf(0u, 42u, 0u, 0u, kc0, kc1);   // k_chain
    h_tf(0u, 42u, 0u, 1u, ks0, ks1);   // k_start

    init_conv_k<<<(NB * ND) / 256, 256>>>(v_data, vd, v, ks0, ks1);

    for (int s = 0; s < KSTEPS; s++) {
        uint32_t nk0, nk1, kh0, kh1, kv0, kv1;
        h_tf(kc0, kc1, 0u, 0u, nk0, nk1);
        h_tf(kc0, kc1, 0u, 1u, kh0, kh1);
        h_tf(kc0, kc1, 0u, 2u, kv0, kv1);
        kc0 = nk0; kc1 = nk1;
        // h = bern(sigmoid(v @ W + cmod)):  B[n][k] = W[k][n] -> WT plane (hi only)
        gemm_mma<0,1,4><<<dim3(8, 128), 256, SMEM_CHAIN>>>(v, WThi, nullptr, cmod, h, nullptr, kh0, kh1);
        // v = bern(sigmoid(h @ W^T + bmod)): B[n][k] = W[n][k] -> W plane (hi only)
        gemm_mma<0,1,4><<<dim3(8, 128), 256, SMEM_CHAIN>>>(h, Whi, nullptr, bmod, v, nullptr, kv0, kv1);
    }

    // free-energy GEMMs keep full hi+lo precision
    gemm_mma<1,2,2><<<dim3(8, 128), 256, SMEM_FE>>>(vd, WThi, WTlo, cmod, nullptr, fed, 0u, 0u);
    gemm_mma<1,2,2><<<dim3(8, 128), 256, SMEM_FE>>>(v,  WThi, WTlo, cmod, nullptr, fem, 0u, 0u);
    dot_bmod_k<<<NB / 8, 256>>>(vd, v, bmod, rowacc);
    finalize_k<<<1, 256>>>(rowacc, fed, fem, (float*)d_out);
}